// round 6
// baseline (speedup 1.0000x reference)
#include <cuda_runtime.h>
#include <cuda_fp16.h>

#define BATCH 131072

typedef unsigned long long u64;

// Scratch (batch-innermost layouts: [feature][B])
__device__ float  g_xT[256 * BATCH];    // 134 MB fp32
__device__ __half g_a1h[768 * BATCH];   // 201 MB fp16  relu(conv1)
__device__ float  g_a2[192 * BATCH];    // 100 MB fp32  relu(conv2)
__device__ float  g_b1eff[768];
__device__ float  g_b2eff[192];

// ---------------------------------------------------------------------------
// packed f32x2 helpers (FFMA2 path — ptxas never auto-generates this)
// ---------------------------------------------------------------------------
__device__ __forceinline__ u64 ffma2(u64 a, u64 b, u64 c) {
    u64 d;
    asm("fma.rn.f32x2 %0, %1, %2, %3;" : "=l"(d) : "l"(a), "l"(b), "l"(c));
    return d;
}
__device__ __forceinline__ u64 pack2(float x) {
    u64 d; unsigned r = __float_as_uint(x);
    asm("mov.b64 %0, {%1, %1};" : "=l"(d) : "r"(r));
    return d;
}
__device__ __forceinline__ u64 pack2v(float lo, float hi) {
    u64 d; unsigned l = __float_as_uint(lo), h = __float_as_uint(hi);
    asm("mov.b64 %0, {%1, %2};" : "=l"(d) : "r"(l), "r"(h));
    return d;
}
__device__ __forceinline__ void unpack2(u64 a, float& lo, float& hi) {
    unsigned l, h;
    asm("mov.b64 {%0, %1}, %2;" : "=r"(l), "=r"(h) : "l"(a));
    lo = __uint_as_float(l); hi = __uint_as_float(h);
}
__device__ __forceinline__ u64 relu2(u64 a) {
    float lo, hi; unpack2(a, lo, hi);
    return pack2v(fmaxf(lo, 0.f), fmaxf(hi, 0.f));
}
__device__ __forceinline__ u64 ldg2(const float* p) {
    return *reinterpret_cast<const u64*>(p);
}
__device__ __forceinline__ void stg2(float* p, u64 v) {
    *reinterpret_cast<u64*>(p) = v;
}
// fp16x2 <-> f32x2
__device__ __forceinline__ unsigned f2h2(u64 v) {
    float lo, hi; unpack2(v, lo, hi);
    __half2 h = __floats2half2_rn(lo, hi);
    return *reinterpret_cast<unsigned*>(&h);
}
__device__ __forceinline__ u64 h2f2(unsigned v) {
    __half2 h = *reinterpret_cast<__half2*>(&v);
    float2 f = __half22float2(h);
    return pack2v(f.x, f.y);
}

// ---------------------------------------------------------------------------
// Fold the constant -1 padding into per-position biases.
// ---------------------------------------------------------------------------
__global__ void prep_kernel(const float* __restrict__ H1w, const float* __restrict__ H1b,
                            const float* __restrict__ H2w, const float* __restrict__ H2b) {
    int tid = threadIdx.x;
    if (tid < 768) {
        int c = tid >> 6, oy = (tid >> 3) & 7, ox = tid & 7;
        float s = 0.f;
        for (int ky = 0; ky < 5; ky++)
            for (int kx = 0; kx < 5; kx++) {
                int ir = 2 * oy + ky - 2, ic = 2 * ox + kx - 2;
                if (ir < 0 || ir >= 16 || ic < 0 || ic >= 16)
                    s += H1w[c * 25 + ky * 5 + kx];
            }
        g_b1eff[tid] = H1b[tid] - s;   // pad value is -1
    } else if (tid < 960) {
        int t = tid - 768;
        int c2 = t >> 4, oy = (t >> 2) & 3, ox = t & 3;
        float s = 0.f;
        for (int ky = 0; ky < 5; ky++)
            for (int kx = 0; kx < 5; kx++) {
                int ir = 2 * oy + ky - 2, ic = 2 * ox + kx - 2;
                if (ir < 0 || ir >= 8 || ic < 0 || ic >= 8)
                    for (int icl = 0; icl < 8; icl++)
                        s += H2w[(c2 * 8 + icl) * 25 + ky * 5 + kx];
            }
        g_b2eff[t] = H2b[t] - s;
    }
}

// ---------------------------------------------------------------------------
// Transpose x [B,256] -> xT [256,B].
// ---------------------------------------------------------------------------
__global__ void transpose_kernel(const float* __restrict__ x, int B) {
    __shared__ float tile[32][33];
    int tx = threadIdx.x, ty = threadIdx.y;
    int b0 = blockIdx.x * 32;
    int e0 = blockIdx.y * 32;
#pragma unroll
    for (int k = 0; k < 4; k++) {
        int s = ty + 8 * k;
        tile[s][tx] = x[(long long)(b0 + s) * 256 + e0 + tx];
    }
    __syncthreads();
#pragma unroll
    for (int k = 0; k < 4; k++) {
        int e = ty + 8 * k;
        g_xT[(long long)(e0 + e) * B + b0 + tx] = tile[tx][e];
    }
}

// ---------------------------------------------------------------------------
// conv1 + relu, 2 samples/thread, FFMA2, fp16 output.
// ox split into compile-time halves (blockIdx.y): row window 5x10 u64.
//   HALF=0: cols 0..9 loaded (taps need 0..8);  local idx = col
//   HALF=1: cols 6..15 loaded (taps need 6..15); local idx = col - 6
// OOB rows zero-filled; OOB col taps pruned at compile time (pad folded into
// b1eff).
// ---------------------------------------------------------------------------
template<int HALF>
__device__ __forceinline__ void conv1_body(const u64* __restrict__ w1p,
                                           const u64* __restrict__ b1p,
                                           long long b2, int B) {
    u64 row[5][10];
#pragma unroll 1
    for (int oy = 0; oy < 8; oy++) {
#pragma unroll
        for (int r = 0; r < 5; r++) {
            int orow = 2 * oy + r - 2;
            if (orow >= 0 && orow < 16) {
#pragma unroll
                for (int j = 0; j < 10; j++) {
                    int col = 6 * HALF + j;
                    row[r][j] = ldg2(&g_xT[(long long)(orow * 16 + col) * B + b2]);
                }
            } else {
#pragma unroll
                for (int j = 0; j < 10; j++) row[r][j] = 0;
            }
        }
#pragma unroll 1
        for (int c = 0; c < 12; c++) {
            u64 acc[4];
#pragma unroll
            for (int ox4 = 0; ox4 < 4; ox4++)
                acc[ox4] = b1p[c * 64 + oy * 8 + 4 * HALF + ox4];
#pragma unroll
            for (int r = 0; r < 5; r++)
#pragma unroll
                for (int kx = 0; kx < 5; kx++) {
                    u64 w = w1p[c * 25 + r * 5 + kx];
#pragma unroll
                    for (int ox4 = 0; ox4 < 4; ox4++) {
                        int col = 8 * HALF + 2 * ox4 + kx - 2;
                        if (col >= 0 && col < 16)
                            acc[ox4] = ffma2(w, row[r][col - 6 * HALF], acc[ox4]);
                    }
                }
#pragma unroll
            for (int ox4 = 0; ox4 < 4; ox4++) {
                long long f = c * 64 + oy * 8 + 4 * HALF + ox4;
                *reinterpret_cast<unsigned*>(&g_a1h[f * B + b2]) = f2h2(relu2(acc[ox4]));
            }
        }
    }
}

__global__ __launch_bounds__(128) void conv1_kernel(const float* __restrict__ H1w, int B) {
    __shared__ u64 w1p[300];
    __shared__ u64 b1p[768];
    int tid = threadIdx.x;
    for (int i = tid; i < 300; i += 128) w1p[i] = pack2(H1w[i]);
    for (int i = tid; i < 768; i += 128) b1p[i] = pack2(g_b1eff[i]);
    __syncthreads();
    long long b2 = (long long)(blockIdx.x * 128 + tid) * 2;
    if (blockIdx.y == 0) conv1_body<0>(w1p, b1p, b2, B);
    else                 conv1_body<1>(w1p, b1p, b2, B);
}

// ---------------------------------------------------------------------------
// grouped conv2 + relu, 2 samples/thread, FFMA2, fp16 input.
// Work split across blocks: blockIdx.y = group g (0..2), blockIdx.z = half
// (oy2 {0,1} vs {2,3}, compile-time template for tap pruning).
// Per (g,half) block: rows for the half's orow range loaded once per icl,
// reused by both output rows. Groups: g0 ic 0-7, g1 ic 4-11, g2 ic {0-3,8-11}.
// ---------------------------------------------------------------------------
template<int HALF>
__device__ __forceinline__ void conv2_body(const u64* __restrict__ w2p,
                                           const u64* __restrict__ b2p,
                                           int g, long long b2, int B) {
    const int base  = HALF ? 2 : 0;   // first loaded orow
    const int nrows = HALF ? 6 : 5;

    u64 acc[2][4][4];
#pragma unroll
    for (int l = 0; l < 2; l++)
#pragma unroll
        for (int oc4 = 0; oc4 < 4; oc4++)
#pragma unroll
            for (int ox = 0; ox < 4; ox++)
                acc[l][oc4][ox] = b2p[oc4 * 8 + l * 4 + ox];

#pragma unroll 1
    for (int icl = 0; icl < 8; icl++) {
        int ic = (g == 2) ? (icl < 4 ? icl : icl + 4)
                          : icl + ((g == 1) ? 4 : 0);
        u64 row[6][8];
#pragma unroll
        for (int lr = 0; lr < 6; lr++) {
            if (lr < nrows) {
                int orow = base + lr;
#pragma unroll
                for (int j = 0; j < 8; j++) {
                    long long f = (ic * 8 + orow) * 8 + j;
                    unsigned raw = *reinterpret_cast<const unsigned*>(&g_a1h[f * B + b2]);
                    row[lr][j] = h2f2(raw);
                }
            }
        }
#pragma unroll
        for (int oc4 = 0; oc4 < 4; oc4++) {
#pragma unroll
            for (int r = 0; r < 5; r++)
#pragma unroll
                for (int kx = 0; kx < 5; kx++) {
                    u64 w = w2p[(oc4 * 8 + icl) * 25 + r * 5 + kx];
#pragma unroll
                    for (int l = 0; l < 2; l++) {
                        int oy2 = 2 * HALF + l;
                        int orow = 2 * oy2 + r - 2;
                        if (orow >= 0 && orow < 8) {
                            int lr = orow - base;   // compile-time
#pragma unroll
                            for (int ox = 0; ox < 4; ox++) {
                                int col = 2 * ox + kx - 2;
                                if (col >= 0 && col < 8)
                                    acc[l][oc4][ox] =
                                        ffma2(w, row[lr][col], acc[l][oc4][ox]);
                            }
                        }
                    }
                }
        }
    }
#pragma unroll
    for (int l = 0; l < 2; l++)
#pragma unroll
        for (int oc4 = 0; oc4 < 4; oc4++)
#pragma unroll
            for (int ox = 0; ox < 4; ox++) {
                long long f = (g * 4 + oc4) * 16 + (2 * HALF + l) * 4 + ox;
                stg2(&g_a2[f * B + b2], relu2(acc[l][oc4][ox]));
            }
}

__global__ __launch_bounds__(128) void conv2_kernel(const float* __restrict__ H2w, int B) {
    __shared__ u64 w2p[800];   // this group's (oc4, icl, tap) weights
    __shared__ u64 b2p[32];    // this (g, half)'s biases: [oc4][l*4+ox]
    int tid = threadIdx.x;
    int g = blockIdx.y;
    for (int i = tid; i < 800; i += 128) w2p[i] = pack2(H2w[g * 800 + i]);
    if (tid < 32) {
        int oc4 = tid >> 3, lx = tid & 7;
        b2p[tid] = pack2(g_b2eff[(g * 4 + oc4) * 16 + blockIdx.z * 8 + lx]);
    }
    __syncthreads();
    long long b2 = (long long)(blockIdx.x * 128 + tid) * 2;
    if (blockIdx.z == 0) conv2_body<0>(w2p, b2p, g, b2, B);
    else                 conv2_body<1>(w2p, b2p, g, b2, B);
}

// ---------------------------------------------------------------------------
// fc: relu(a2 @ H3w + H3b) @ outw + outb.  2 samples/thread, FFMA2 layer 1.
// ---------------------------------------------------------------------------
__global__ __launch_bounds__(128) void fc_kernel(const float* __restrict__ H3w,
                                                 const float* __restrict__ H3b,
                                                 const float* __restrict__ outw,
                                                 const float* __restrict__ outb,
                                                 float* __restrict__ out, int B) {
    __shared__ u64 w3p[5760];          // 46 KB (w,w) pairs
    __shared__ float w4s[300], b3s[30], b4s[10];
    int tid = threadIdx.x;
    for (int i = tid; i < 5760; i += 128) w3p[i] = pack2(H3w[i]);
    for (int i = tid; i < 300; i += 128) w4s[i] = outw[i];
    if (tid < 30) b3s[tid] = H3b[tid];
    if (tid < 10) b4s[tid] = outb[tid];
    __syncthreads();
    long long b2 = (long long)(blockIdx.x * 128 + tid) * 2;

    u64 h[30];
#pragma unroll
    for (int j = 0; j < 30; j++) h[j] = pack2(b3s[j]);
#pragma unroll 4
    for (int i = 0; i < 192; i++) {
        u64 v = ldg2(&g_a2[(long long)i * B + b2]);
#pragma unroll
        for (int j = 0; j < 30; j++)
            h[j] = ffma2(w3p[i * 30 + j], v, h[j]);
    }
    float hA[30], hB[30];
#pragma unroll
    for (int j = 0; j < 30; j++) {
        float lo, hi; unpack2(h[j], lo, hi);
        hA[j] = fmaxf(lo, 0.f); hB[j] = fmaxf(hi, 0.f);
    }
    float oA[10], oB[10];
#pragma unroll
    for (int k = 0; k < 10; k++) { oA[k] = b4s[k]; oB[k] = b4s[k]; }
#pragma unroll
    for (int j = 0; j < 30; j++)
#pragma unroll
        for (int k = 0; k < 10; k++) {
            float w = w4s[j * 10 + k];
            oA[k] += w * hA[j];
            oB[k] += w * hB[j];
        }
#pragma unroll
    for (int k = 0; k < 10; k++) {
        out[b2 * 10 + k]       = oA[k];
        out[(b2 + 1) * 10 + k] = oB[k];
    }
}

// ---------------------------------------------------------------------------
extern "C" void kernel_launch(void* const* d_in, const int* in_sizes, int n_in,
                              void* d_out, int out_size) {
    const float* x    = (const float*)d_in[0];
    const float* H1w  = (const float*)d_in[1];
    const float* H1b  = (const float*)d_in[2];
    const float* H2w  = (const float*)d_in[3];
    const float* H2b  = (const float*)d_in[4];
    const float* H3w  = (const float*)d_in[5];
    const float* H3b  = (const float*)d_in[6];
    const float* outw = (const float*)d_in[7];
    const float* outb = (const float*)d_in[8];
    float* out = (float*)d_out;

    int B = in_sizes[0] / 256;   // 131072
    int P = B / 2;               // sample pairs

    prep_kernel<<<1, 1024>>>(H1w, H1b, H2w, H2b);
    transpose_kernel<<<dim3(B / 32, 8), dim3(32, 8)>>>(x, B);
    conv1_kernel<<<dim3(P / 128, 2), 128>>>(H1w, B);
    conv2_kernel<<<dim3(P / 128, 3, 2), 128>>>(H2w, B);
    fc_kernel<<<P / 128, 128>>>(H3w, H3b, outw, outb, out, B);
}